// round 8
// baseline (speedup 1.0000x reference)
#include <cuda_runtime.h>
#include <cuda_bf16.h>

// ---------------------------------------------------------------------------
// SelfAttentionBlock: graph attention with per-edge RPE.
// N=50000, E=800000, DIM=256, H=16, D=8, DH=128, IN_RPE=18. SCALE=1/sqrt(8).
//
// Pipeline (6 kernels):
//   K0 init      : zero d_out, zero g_sum
//   K1a convert_x: x (fp32) -> xh + xl (bf16 split)
//   K1b convert_w: Wqkv (fp32) -> wht + wlt (bf16 split, transposed [n][k])
//   K1  gemm_mma : g_qkv = x @ Wqkv + bias via bf16x3 mma.sync (fp32 acc)
//   K2  compat   : persistent warps, RPE weights in registers, 4 warps/edge
//                  (32 dims each, 36 weight regs -> 4 CTAs/SM occupancy)
//   K3  message  : out[s] += (ex/(den[s]+eps)) * v[t]  via red.global.v4.f32
// ---------------------------------------------------------------------------

#define MAX_N 50000
#define MAX_E 800000
#define HH    16
#define SCALE 0.35355339059327373f   // 8^-0.5

__device__ float g_qkv[(size_t)MAX_N * 512];   // [q(128) | k(128) | v(256)]
__device__ float g_ex [(size_t)MAX_E * HH];    // exp(compat)
__device__ float g_sum[(size_t)MAX_N * HH];    // softmax denominators

// bf16-split scratch for the tensor-core GEMM
__device__ __nv_bfloat16 g_xh[(size_t)MAX_N * 256];
__device__ __nv_bfloat16 g_xl[(size_t)MAX_N * 256];
__device__ __nv_bfloat16 g_wht[512 * 256];     // transposed: [n][k]
__device__ __nv_bfloat16 g_wlt[512 * 256];

// Vectorized global reduction (sm_90+): one instruction adds 4 floats.
__device__ __forceinline__ void red_add_v4(float* addr, float a, float b,
                                           float c, float d) {
    asm volatile("red.global.v4.f32.add [%0], {%1, %2, %3, %4};"
                 :: "l"(addr), "f"(a), "f"(b), "f"(c), "f"(d)
                 : "memory");
}

// cp.async 16B with zero-fill when srcBytes==0
__device__ __forceinline__ void cp_async_16(unsigned dst, const void* src,
                                            int srcBytes) {
    asm volatile("cp.async.cg.shared.global [%0], [%1], 16, %2;"
                 :: "r"(dst), "l"(src), "r"(srcBytes));
}

#define MMA16816(c, a0, a1, a2, a3, b0, b1)                                   \
    asm volatile("mma.sync.aligned.m16n8k16.row.col.f32.bf16.bf16.f32 "       \
                 "{%0,%1,%2,%3}, {%4,%5,%6,%7}, {%8,%9}, {%0,%1,%2,%3};"      \
                 : "+f"((c)[0]), "+f"((c)[1]), "+f"((c)[2]), "+f"((c)[3])     \
                 : "r"(a0), "r"(a1), "r"(a2), "r"(a3), "r"(b0), "r"(b1))

// --------------------------- K0: init --------------------------------------
__global__ void k_init(float4* __restrict__ out, int n_out4, int n_nodes) {
    int i = blockIdx.x * blockDim.x + threadIdx.x;
    if (i < n_out4) out[i] = make_float4(0.f, 0.f, 0.f, 0.f);
    if (i < n_nodes * HH) g_sum[i] = 0.0f;
}

// --------------------------- K1a: split-convert x ---------------------------
__global__ void k_convert_x(const float* __restrict__ x, int n) {
    int i = blockIdx.x * blockDim.x + threadIdx.x;
    if (i >= n) return;
    float v = x[i];
    __nv_bfloat16 h = __float2bfloat16(v);
    g_xh[i] = h;
    g_xl[i] = __float2bfloat16(v - __bfloat162float(h));
}

// --------------------------- K1b: split-convert + transpose W ---------------
__global__ void k_convert_w(const float* __restrict__ W) {
    int i = blockIdx.x * blockDim.x + threadIdx.x;   // i = k*512 + n
    if (i >= 256 * 512) return;
    int n = i & 511;
    int k = i >> 9;
    float v = W[i];
    __nv_bfloat16 h = __float2bfloat16(v);
    g_wht[n * 256 + k] = h;
    g_wlt[n * 256 + k] = __float2bfloat16(v - __bfloat162float(h));
}

// --------------------------- K1: bf16x3 tensor-core GEMM --------------------
// C[M,512] = X[M,256] @ W[256,512] + bias, via Xh*Wh + Xh*Wl + Xl*Wh.
// CTA tile 128x128, K chunk 32, 8 warps (2x4), warp tile 64x32.
#define SMSTRIDE 40
__global__ void __launch_bounds__(256) k_gemm_mma(
    const float* __restrict__ bias, int M)
{
    __shared__ __nv_bfloat16 Ah[128 * SMSTRIDE];
    __shared__ __nv_bfloat16 Al[128 * SMSTRIDE];
    __shared__ __nv_bfloat16 Bh[128 * SMSTRIDE];
    __shared__ __nv_bfloat16 Bl[128 * SMSTRIDE];

    const int tid  = threadIdx.x;
    const int wid  = tid >> 5;
    const int lane = tid & 31;
    const int g    = lane >> 2;       // group id 0..7
    const int tg   = lane & 3;        // thread in group
    const int wm   = wid >> 2;        // 0..1
    const int wn   = wid & 3;         // 0..3

    const int rowTile = blockIdx.y * 128;
    const int colTile = blockIdx.x * 128;

    const unsigned AhU = (unsigned)__cvta_generic_to_shared(Ah);
    const unsigned AlU = (unsigned)__cvta_generic_to_shared(Al);
    const unsigned BhU = (unsigned)__cvta_generic_to_shared(Bh);
    const unsigned BlU = (unsigned)__cvta_generic_to_shared(Bl);

    float acc[4][4][4];
#pragma unroll
    for (int mf = 0; mf < 4; mf++)
#pragma unroll
        for (int nf = 0; nf < 4; nf++)
#pragma unroll
            for (int r = 0; r < 4; r++) acc[mf][nf][r] = 0.0f;

#pragma unroll 1
    for (int kt = 0; kt < 8; kt++) {
        const int k0 = kt * 32;
#pragma unroll
        for (int j = 0; j < 2; j++) {
            int c   = tid + j * 256;     // 0..511
            int r   = c >> 2;            // row 0..127
            int off = c & 3;             // 16B chunk within 64B row-slice
            unsigned soff = (unsigned)(r * SMSTRIDE * 2 + off * 16);

            int rowG = rowTile + r;
            int nb   = (rowG < M) ? 16 : 0;
            cp_async_16(AhU + soff, g_xh + (size_t)rowG * 256 + k0 + off * 8, nb);
            cp_async_16(AlU + soff, g_xl + (size_t)rowG * 256 + k0 + off * 8, nb);

            int nG = colTile + r;
            cp_async_16(BhU + soff, g_wht + (size_t)nG * 256 + k0 + off * 8, 16);
            cp_async_16(BlU + soff, g_wlt + (size_t)nG * 256 + k0 + off * 8, 16);
        }
        asm volatile("cp.async.commit_group;");
        asm volatile("cp.async.wait_group 0;");
        __syncthreads();

#pragma unroll
        for (int ks = 0; ks < 2; ks++) {
            const int kc = ks * 16 + tg * 2;

            unsigned bh[4][2], bl[4][2];
#pragma unroll
            for (int nf = 0; nf < 4; nf++) {
                int nb0 = (wn * 32 + nf * 8 + g) * SMSTRIDE;
                bh[nf][0] = *(const unsigned*)&Bh[nb0 + kc];
                bh[nf][1] = *(const unsigned*)&Bh[nb0 + kc + 8];
                bl[nf][0] = *(const unsigned*)&Bl[nb0 + kc];
                bl[nf][1] = *(const unsigned*)&Bl[nb0 + kc + 8];
            }
#pragma unroll
            for (int mf = 0; mf < 4; mf++) {
                int r0 = (wm * 64 + mf * 16 + g) * SMSTRIDE;
                int r8 = r0 + 8 * SMSTRIDE;
                unsigned ah0 = *(const unsigned*)&Ah[r0 + kc];
                unsigned ah1 = *(const unsigned*)&Ah[r8 + kc];
                unsigned ah2 = *(const unsigned*)&Ah[r0 + kc + 8];
                unsigned ah3 = *(const unsigned*)&Ah[r8 + kc + 8];
                unsigned al0 = *(const unsigned*)&Al[r0 + kc];
                unsigned al1 = *(const unsigned*)&Al[r8 + kc];
                unsigned al2 = *(const unsigned*)&Al[r0 + kc + 8];
                unsigned al3 = *(const unsigned*)&Al[r8 + kc + 8];
#pragma unroll
                for (int nf = 0; nf < 4; nf++) {
                    MMA16816(acc[mf][nf], ah0, ah1, ah2, ah3,
                             bh[nf][0], bh[nf][1]);
                    MMA16816(acc[mf][nf], ah0, ah1, ah2, ah3,
                             bl[nf][0], bl[nf][1]);
                    MMA16816(acc[mf][nf], al0, al1, al2, al3,
                             bh[nf][0], bh[nf][1]);
                }
            }
        }
        __syncthreads();
    }

#pragma unroll
    for (int mf = 0; mf < 4; mf++) {
        int row0 = rowTile + wm * 64 + mf * 16 + g;
        int row1 = row0 + 8;
#pragma unroll
        for (int nf = 0; nf < 4; nf++) {
            int col = colTile + wn * 32 + nf * 8 + tg * 2;
            float2 bb = *(const float2*)(bias + col);
            if (row0 < M) {
                float2 o = make_float2(acc[mf][nf][0] + bb.x,
                                       acc[mf][nf][1] + bb.y);
                *(float2*)(g_qkv + (size_t)row0 * 512 + col) = o;
            }
            if (row1 < M) {
                float2 o = make_float2(acc[mf][nf][2] + bb.x,
                                       acc[mf][nf][3] + bb.y);
                *(float2*)(g_qkv + (size_t)row1 * 512 + col) = o;
            }
        }
    }
}

// --------------------------- K2: edge compat (register weights) -------------
// Persistent grid-stride warps, 4 warps per edge. Warp quarter q owns dims
// [32q, 32q+32) = heads [4q, 4q+4); lane owns ONE dim. RPE weights: 36
// registers/lane, loaded once. ~64 regs -> 4 CTAs/SM (32 warps/SM) for
// latency hiding of the q/k gathers. No shared memory in the edge loop.
__global__ void __launch_bounds__(256, 4) k_edge_compat(
    const int* __restrict__ ei, const float* __restrict__ ea,
    const float* __restrict__ Wk, const float* __restrict__ bk,
    const float* __restrict__ Wq, const float* __restrict__ bq, int E)
{
    const int gwid    = (blockIdx.x * blockDim.x + threadIdx.x) >> 5;
    const int lane    = threadIdx.x & 31;
    const int quarter = gwid & 3;
    const int c       = quarter * 32 + lane;     // dim owned by this lane

    // Load RPE weights into registers (once per warp lifetime).
    float wq[18], wk[18];
#pragma unroll
    for (int i = 0; i < 18; i++) {
        wq[i] = Wq[i * 128 + c];
        wk[i] = Wk[i * 128 + c];
    }
    const float bqv = bq[c];
    const float bkv = bk[c];
    const int h = quarter * 4 + (lane >> 3);     // head written by lead lanes

    const int nWarps = (gridDim.x * blockDim.x) >> 5;
    const int stride = nWarps >> 2;

    for (int e = gwid >> 2; e < E; e += stride) {
        int s = ei[e];
        int t = ei[E + e];
        float eal = (lane < 18) ? ea[(size_t)e * 18 + lane] : 0.0f;

        float aq = bqv, ak = bkv;
#pragma unroll
        for (int i = 0; i < 18; i++) {
            float v = __shfl_sync(0xffffffffu, eal, i);
            aq += v * wq[i];
            ak += v * wk[i];
        }

        float qv = g_qkv[(size_t)s * 512 + c];
        float kv = g_qkv[(size_t)t * 512 + 128 + c];

        float p = (qv * SCALE + aq) * (kv + ak);
        p += __shfl_xor_sync(0xffffffffu, p, 1);
        p += __shfl_xor_sync(0xffffffffu, p, 2);
        p += __shfl_xor_sync(0xffffffffu, p, 4);

        if ((lane & 7) == 0) {
            float ex = __expf(p);          // safe: |compat| << 88
            g_ex[(size_t)e * HH + h] = ex;
            atomicAdd(&g_sum[s * HH + h], ex);
        }
    }
}

// --------------------------- K3: weighted message scatter -------------------
// One warp per edge. Lane j handles out dims [8j, 8j+8) -> head j/2.
__global__ void __launch_bounds__(256) k_message(
    const int* __restrict__ ei, float* __restrict__ out, int E)
{
    int e = blockIdx.x * 8 + (threadIdx.x >> 5);
    if (e >= E) return;
    int lane = threadIdx.x & 31;

    int s = ei[e];
    int t = ei[E + e];
    int h = lane >> 1;

    float ex  = g_ex[(size_t)e * HH + h];
    float den = g_sum[s * HH + h];
    float a   = ex / (den + 1e-16f);

    const float* vp = g_qkv + (size_t)t * 512 + 256 + lane * 8;
    float4 v0 = *(const float4*)vp;
    float4 v1 = *(const float4*)(vp + 4);

    float* op = out + (size_t)s * 256 + lane * 8;
    red_add_v4(op,     a * v0.x, a * v0.y, a * v0.z, a * v0.w);
    red_add_v4(op + 4, a * v1.x, a * v1.y, a * v1.z, a * v1.w);
}

// ---------------------------------------------------------------------------
extern "C" void kernel_launch(void* const* d_in, const int* in_sizes, int n_in,
                              void* d_out, int out_size)
{
    const float* x    = (const float*)d_in[0];
    const int*   ei   = (const int*)d_in[1];
    const float* ea   = (const float*)d_in[2];
    const float* Wqkv = (const float*)d_in[3];
    const float* bqkv = (const float*)d_in[4];
    const float* Wk   = (const float*)d_in[5];
    const float* bk   = (const float*)d_in[6];
    const float* Wq   = (const float*)d_in[7];
    const float* bq   = (const float*)d_in[8];
    float*       out  = (float*)d_out;

    int M = in_sizes[0] / 256;   // num nodes
    int E = in_sizes[1] / 2;     // num edges

    int n_out4 = M * 64;   // M*256 floats / 4
    k_init<<<(n_out4 + 255) / 256, 256>>>((float4*)out, n_out4, M);

    int nx = M * 256;
    k_convert_x<<<(nx + 255) / 256, 256>>>(x, nx);
    k_convert_w<<<(256 * 512 + 255) / 256, 256>>>(Wqkv);

    dim3 g1(4, (M + 127) / 128);
    k_gemm_mma<<<g1, 256>>>(bqkv, M);

    // Persistent grid-stride: 4 warps per edge (one 32-dim quarter each).
    k_edge_compat<<<1184, 256>>>(ei, ea, Wk, bk, Wq, bq, E);

    k_message<<<(E + 7) / 8, 256>>>(ei, out, E);
}

// round 9
// speedup vs baseline: 1.2158x; 1.2158x over previous
#include <cuda_runtime.h>
#include <cuda_bf16.h>

// ---------------------------------------------------------------------------
// SelfAttentionBlock: graph attention with per-edge RPE.
// N=50000, E=800000, DIM=256, H=16, D=8, DH=128, IN_RPE=18. SCALE=1/sqrt(8).
//
// Pipeline (6 kernels):
//   K0 init      : zero d_out, zero g_sum
//   K1a convert_x: x (fp32) -> xh + xl (bf16 split)
//   K1b convert_w: Wqkv (fp32) -> wht + wlt (bf16 split, transposed [n][k])
//   K1  gemm_mma : g_qkv = x @ Wqkv + bias via bf16x3 mma.sync (fp32 acc)
//   K2  compat   : persistent warps, RPE weights in registers, 2 warps/edge,
//                  2-edge software pipeline for gather-latency hiding
//   K3  message  : out[s] += (ex/(den[s]+eps)) * v[t]  via red.global.v4.f32
// ---------------------------------------------------------------------------

#define MAX_N 50000
#define MAX_E 800000
#define HH    16
#define SCALE 0.35355339059327373f   // 8^-0.5

__device__ float g_qkv[(size_t)MAX_N * 512];   // [q(128) | k(128) | v(256)]
__device__ float g_ex [(size_t)MAX_E * HH];    // exp(compat)
__device__ float g_sum[(size_t)MAX_N * HH];    // softmax denominators

// bf16-split scratch for the tensor-core GEMM
__device__ __nv_bfloat16 g_xh[(size_t)MAX_N * 256];
__device__ __nv_bfloat16 g_xl[(size_t)MAX_N * 256];
__device__ __nv_bfloat16 g_wht[512 * 256];     // transposed: [n][k]
__device__ __nv_bfloat16 g_wlt[512 * 256];

// Vectorized global reduction (sm_90+): one instruction adds 4 floats.
__device__ __forceinline__ void red_add_v4(float* addr, float a, float b,
                                           float c, float d) {
    asm volatile("red.global.v4.f32.add [%0], {%1, %2, %3, %4};"
                 :: "l"(addr), "f"(a), "f"(b), "f"(c), "f"(d)
                 : "memory");
}

// cp.async 16B with zero-fill when srcBytes==0
__device__ __forceinline__ void cp_async_16(unsigned dst, const void* src,
                                            int srcBytes) {
    asm volatile("cp.async.cg.shared.global [%0], [%1], 16, %2;"
                 :: "r"(dst), "l"(src), "r"(srcBytes));
}

#define MMA16816(c, a0, a1, a2, a3, b0, b1)                                   \
    asm volatile("mma.sync.aligned.m16n8k16.row.col.f32.bf16.bf16.f32 "       \
                 "{%0,%1,%2,%3}, {%4,%5,%6,%7}, {%8,%9}, {%0,%1,%2,%3};"      \
                 : "+f"((c)[0]), "+f"((c)[1]), "+f"((c)[2]), "+f"((c)[3])     \
                 : "r"(a0), "r"(a1), "r"(a2), "r"(a3), "r"(b0), "r"(b1))

// --------------------------- K0: init --------------------------------------
__global__ void k_init(float4* __restrict__ out, int n_out4, int n_nodes) {
    int i = blockIdx.x * blockDim.x + threadIdx.x;
    if (i < n_out4) out[i] = make_float4(0.f, 0.f, 0.f, 0.f);
    if (i < n_nodes * HH) g_sum[i] = 0.0f;
}

// --------------------------- K1a: split-convert x ---------------------------
__global__ void k_convert_x(const float* __restrict__ x, int n) {
    int i = blockIdx.x * blockDim.x + threadIdx.x;
    if (i >= n) return;
    float v = x[i];
    __nv_bfloat16 h = __float2bfloat16(v);
    g_xh[i] = h;
    g_xl[i] = __float2bfloat16(v - __bfloat162float(h));
}

// --------------------------- K1b: split-convert + transpose W ---------------
__global__ void k_convert_w(const float* __restrict__ W) {
    int i = blockIdx.x * blockDim.x + threadIdx.x;   // i = k*512 + n
    if (i >= 256 * 512) return;
    int n = i & 511;
    int k = i >> 9;
    float v = W[i];
    __nv_bfloat16 h = __float2bfloat16(v);
    g_wht[n * 256 + k] = h;
    g_wlt[n * 256 + k] = __float2bfloat16(v - __bfloat162float(h));
}

// --------------------------- K1: bf16x3 tensor-core GEMM --------------------
// C[M,512] = X[M,256] @ W[256,512] + bias, via Xh*Wh + Xh*Wl + Xl*Wh.
// CTA tile 128x128, K chunk 32, 8 warps (2x4), warp tile 64x32.
#define SMSTRIDE 40
__global__ void __launch_bounds__(256) k_gemm_mma(
    const float* __restrict__ bias, int M)
{
    __shared__ __nv_bfloat16 Ah[128 * SMSTRIDE];
    __shared__ __nv_bfloat16 Al[128 * SMSTRIDE];
    __shared__ __nv_bfloat16 Bh[128 * SMSTRIDE];
    __shared__ __nv_bfloat16 Bl[128 * SMSTRIDE];

    const int tid  = threadIdx.x;
    const int wid  = tid >> 5;
    const int lane = tid & 31;
    const int g    = lane >> 2;       // group id 0..7
    const int tg   = lane & 3;        // thread in group
    const int wm   = wid >> 2;        // 0..1
    const int wn   = wid & 3;         // 0..3

    const int rowTile = blockIdx.y * 128;
    const int colTile = blockIdx.x * 128;

    const unsigned AhU = (unsigned)__cvta_generic_to_shared(Ah);
    const unsigned AlU = (unsigned)__cvta_generic_to_shared(Al);
    const unsigned BhU = (unsigned)__cvta_generic_to_shared(Bh);
    const unsigned BlU = (unsigned)__cvta_generic_to_shared(Bl);

    float acc[4][4][4];
#pragma unroll
    for (int mf = 0; mf < 4; mf++)
#pragma unroll
        for (int nf = 0; nf < 4; nf++)
#pragma unroll
            for (int r = 0; r < 4; r++) acc[mf][nf][r] = 0.0f;

#pragma unroll 1
    for (int kt = 0; kt < 8; kt++) {
        const int k0 = kt * 32;
#pragma unroll
        for (int j = 0; j < 2; j++) {
            int c   = tid + j * 256;     // 0..511
            int r   = c >> 2;            // row 0..127
            int off = c & 3;             // 16B chunk within 64B row-slice
            unsigned soff = (unsigned)(r * SMSTRIDE * 2 + off * 16);

            int rowG = rowTile + r;
            int nb   = (rowG < M) ? 16 : 0;
            cp_async_16(AhU + soff, g_xh + (size_t)rowG * 256 + k0 + off * 8, nb);
            cp_async_16(AlU + soff, g_xl + (size_t)rowG * 256 + k0 + off * 8, nb);

            int nG = colTile + r;
            cp_async_16(BhU + soff, g_wht + (size_t)nG * 256 + k0 + off * 8, 16);
            cp_async_16(BlU + soff, g_wlt + (size_t)nG * 256 + k0 + off * 8, 16);
        }
        asm volatile("cp.async.commit_group;");
        asm volatile("cp.async.wait_group 0;");
        __syncthreads();

#pragma unroll
        for (int ks = 0; ks < 2; ks++) {
            const int kc = ks * 16 + tg * 2;

            unsigned bh[4][2], bl[4][2];
#pragma unroll
            for (int nf = 0; nf < 4; nf++) {
                int nb0 = (wn * 32 + nf * 8 + g) * SMSTRIDE;
                bh[nf][0] = *(const unsigned*)&Bh[nb0 + kc];
                bh[nf][1] = *(const unsigned*)&Bh[nb0 + kc + 8];
                bl[nf][0] = *(const unsigned*)&Bl[nb0 + kc];
                bl[nf][1] = *(const unsigned*)&Bl[nb0 + kc + 8];
            }
#pragma unroll
            for (int mf = 0; mf < 4; mf++) {
                int r0 = (wm * 64 + mf * 16 + g) * SMSTRIDE;
                int r8 = r0 + 8 * SMSTRIDE;
                unsigned ah0 = *(const unsigned*)&Ah[r0 + kc];
                unsigned ah1 = *(const unsigned*)&Ah[r8 + kc];
                unsigned ah2 = *(const unsigned*)&Ah[r0 + kc + 8];
                unsigned ah3 = *(const unsigned*)&Ah[r8 + kc + 8];
                unsigned al0 = *(const unsigned*)&Al[r0 + kc];
                unsigned al1 = *(const unsigned*)&Al[r8 + kc];
                unsigned al2 = *(const unsigned*)&Al[r0 + kc + 8];
                unsigned al3 = *(const unsigned*)&Al[r8 + kc + 8];
#pragma unroll
                for (int nf = 0; nf < 4; nf++) {
                    MMA16816(acc[mf][nf], ah0, ah1, ah2, ah3,
                             bh[nf][0], bh[nf][1]);
                    MMA16816(acc[mf][nf], ah0, ah1, ah2, ah3,
                             bl[nf][0], bl[nf][1]);
                    MMA16816(acc[mf][nf], al0, al1, al2, al3,
                             bh[nf][0], bh[nf][1]);
                }
            }
        }
        __syncthreads();
    }

#pragma unroll
    for (int mf = 0; mf < 4; mf++) {
        int row0 = rowTile + wm * 64 + mf * 16 + g;
        int row1 = row0 + 8;
#pragma unroll
        for (int nf = 0; nf < 4; nf++) {
            int col = colTile + wn * 32 + nf * 8 + tg * 2;
            float2 bb = *(const float2*)(bias + col);
            if (row0 < M) {
                float2 o = make_float2(acc[mf][nf][0] + bb.x,
                                       acc[mf][nf][1] + bb.y);
                *(float2*)(g_qkv + (size_t)row0 * 512 + col) = o;
            }
            if (row1 < M) {
                float2 o = make_float2(acc[mf][nf][2] + bb.x,
                                       acc[mf][nf][3] + bb.y);
                *(float2*)(g_qkv + (size_t)row1 * 512 + col) = o;
            }
        }
    }
}

// --------------------------- K2: edge compat (register weights) -------------
// Persistent grid-stride warps, 2 warps per edge (parity owns a 64-dim half =
// 8 heads; lane owns 2 dims; 72 weight regs/lane). 2-edge software pipeline:
// both edges' ei/ea/q/k loads are issued before either edge's compute, so the
// gather latency chains overlap (MLP x2) despite 2-CTA/SM occupancy.
__global__ void __launch_bounds__(256, 2) k_edge_compat(
    const int* __restrict__ ei, const float* __restrict__ ea,
    const float* __restrict__ Wk, const float* __restrict__ bk,
    const float* __restrict__ Wq, const float* __restrict__ bq, int E)
{
    const int gwid   = (blockIdx.x * blockDim.x + threadIdx.x) >> 5;
    const int lane   = threadIdx.x & 31;
    const int parity = gwid & 1;
    const int c      = parity * 64 + lane * 2;   // dim pair owned by this lane

    // Load RPE weights into registers (once per warp lifetime).
    float wq0[18], wq1[18], wk0[18], wk1[18];
#pragma unroll
    for (int i = 0; i < 18; i++) {
        float2 t = *(const float2*)(Wq + i * 128 + c);
        wq0[i] = t.x; wq1[i] = t.y;
        float2 u = *(const float2*)(Wk + i * 128 + c);
        wk0[i] = u.x; wk1[i] = u.y;
    }
    const float2 bqv = *(const float2*)(bq + c);
    const float2 bkv = *(const float2*)(bk + c);
    const int h = parity * 8 + (lane >> 2);      // head written by lead lanes

    const int nWarps = (gridDim.x * blockDim.x) >> 5;
    const int stride = nWarps >> 1;              // edge stride per warp-pair
    const int step   = stride * 2;               // 2 edges per iteration

    for (int e = gwid >> 1; e < E; e += step) {
        const int e1 = e + stride;
        const bool has1 = (e1 < E);
        const int e1c = has1 ? e1 : e;           // clamp: loads stay in-bounds

        // ---- issue ALL loads for both edges first (overlap latency) ----
        int s0 = ei[e];
        int t0 = ei[E + e];
        int s1 = ei[e1c];
        int t1 = ei[E + e1c];

        float eal0 = (lane < 18) ? __ldg(ea + (size_t)e   * 18 + lane) : 0.0f;
        float eal1 = (lane < 18) ? __ldg(ea + (size_t)e1c * 18 + lane) : 0.0f;

        float2 q0 = *(const float2*)(g_qkv + (size_t)s0 * 512 + c);
        float2 k0 = *(const float2*)(g_qkv + (size_t)t0 * 512 + 128 + c);
        float2 q1 = *(const float2*)(g_qkv + (size_t)s1 * 512 + c);
        float2 k1 = *(const float2*)(g_qkv + (size_t)t1 * 512 + 128 + c);

        // ---- edge 0 compute ----
        float aq0 = bqv.x, aq1 = bqv.y, ak0 = bkv.x, ak1 = bkv.y;
        float cq0 = bqv.x, cq1 = bqv.y, ck0 = bkv.x, ck1 = bkv.y;
#pragma unroll
        for (int i = 0; i < 18; i++) {
            float v0 = __shfl_sync(0xffffffffu, eal0, i);
            float v1 = __shfl_sync(0xffffffffu, eal1, i);
            aq0 += v0 * wq0[i]; aq1 += v0 * wq1[i];
            ak0 += v0 * wk0[i]; ak1 += v0 * wk1[i];
            cq0 += v1 * wq0[i]; cq1 += v1 * wq1[i];
            ck0 += v1 * wk0[i]; ck1 += v1 * wk1[i];
        }

        float p0 = (q0.x * SCALE + aq0) * (k0.x + ak0)
                 + (q0.y * SCALE + aq1) * (k0.y + ak1);
        p0 += __shfl_xor_sync(0xffffffffu, p0, 1);
        p0 += __shfl_xor_sync(0xffffffffu, p0, 2);

        float p1 = (q1.x * SCALE + cq0) * (k1.x + ck0)
                 + (q1.y * SCALE + cq1) * (k1.y + ck1);
        p1 += __shfl_xor_sync(0xffffffffu, p1, 1);
        p1 += __shfl_xor_sync(0xffffffffu, p1, 2);

        if ((lane & 3) == 0) {
            float ex0 = __expf(p0);        // safe: |compat| << 88
            g_ex[(size_t)e * HH + h] = ex0;
            atomicAdd(&g_sum[s0 * HH + h], ex0);
            if (has1) {
                float ex1 = __expf(p1);
                g_ex[(size_t)e1 * HH + h] = ex1;
                atomicAdd(&g_sum[s1 * HH + h], ex1);
            }
        }
    }
}

// --------------------------- K3: weighted message scatter -------------------
// One warp per edge. Lane j handles out dims [8j, 8j+8) -> head j/2.
__global__ void __launch_bounds__(256) k_message(
    const int* __restrict__ ei, float* __restrict__ out, int E)
{
    int e = blockIdx.x * 8 + (threadIdx.x >> 5);
    if (e >= E) return;
    int lane = threadIdx.x & 31;

    int s = ei[e];
    int t = ei[E + e];
    int h = lane >> 1;

    float ex  = g_ex[(size_t)e * HH + h];
    float den = g_sum[s * HH + h];
    float a   = ex / (den + 1e-16f);

    const float* vp = g_qkv + (size_t)t * 512 + 256 + lane * 8;
    float4 v0 = *(const float4*)vp;
    float4 v1 = *(const float4*)(vp + 4);

    float* op = out + (size_t)s * 256 + lane * 8;
    red_add_v4(op,     a * v0.x, a * v0.y, a * v0.z, a * v0.w);
    red_add_v4(op + 4, a * v1.x, a * v1.y, a * v1.z, a * v1.w);
}

// ---------------------------------------------------------------------------
extern "C" void kernel_launch(void* const* d_in, const int* in_sizes, int n_in,
                              void* d_out, int out_size)
{
    const float* x    = (const float*)d_in[0];
    const int*   ei   = (const int*)d_in[1];
    const float* ea   = (const float*)d_in[2];
    const float* Wqkv = (const float*)d_in[3];
    const float* bqkv = (const float*)d_in[4];
    const float* Wk   = (const float*)d_in[5];
    const float* bk   = (const float*)d_in[6];
    const float* Wq   = (const float*)d_in[7];
    const float* bq   = (const float*)d_in[8];
    float*       out  = (float*)d_out;

    int M = in_sizes[0] / 256;   // num nodes
    int E = in_sizes[1] / 2;     // num edges

    int n_out4 = M * 64;   // M*256 floats / 4
    k_init<<<(n_out4 + 255) / 256, 256>>>((float4*)out, n_out4, M);

    int nx = M * 256;
    k_convert_x<<<(nx + 255) / 256, 256>>>(x, nx);
    k_convert_w<<<(256 * 512 + 255) / 256, 256>>>(Wqkv);

    dim3 g1(4, (M + 127) / 128);
    k_gemm_mma<<<g1, 256>>>(bqkv, M);

    // Persistent grid-stride: 2 warps per edge, 2-edge pipeline per warp.
    k_edge_compat<<<1184, 256>>>(ei, ea, Wk, bk, Wq, bq, E);

    k_message<<<(E + 7) / 8, 256>>>(ei, out, E);
}